// round 2
// baseline (speedup 1.0000x reference)
#include <cuda_runtime.h>
#include <math.h>

#define NMAX 50000
#define EMAX 800000

// scratch (device globals — no allocation allowed)
__device__ float g_fs[NMAX * 128];
__device__ float g_fd[NMAX * 128];
__device__ int   g_deg[NMAX];
__device__ int   g_off[NMAX + 1];
__device__ int   g_ptr[NMAX];
__device__ int   g_csr[EMAX];

// ---------------------------------------------------------------------------
// SGEMM: out = x @ W + b, x [n,128], W [128,128]. blockIdx.y: 0 -> fs, 1 -> fd
// tile 128x128, 256 threads, 8x8 per thread, k-chunks of 32
// ---------------------------------------------------------------------------
__global__ void sgemm_kernel(const float* __restrict__ x,
                             const float* __restrict__ Wsrc, const float* __restrict__ bsrc,
                             const float* __restrict__ Wdst, const float* __restrict__ bdst,
                             int n) {
    const float* W = (blockIdx.y == 0) ? Wsrc : Wdst;
    const float* b = (blockIdx.y == 0) ? bsrc : bdst;
    float* out = (blockIdx.y == 0) ? g_fs : g_fd;

    __shared__ float xs[32][132];  // [k][row], padded
    __shared__ float ws[32][132];  // [k][col], padded

    int row0 = blockIdx.x * 128;
    int tid = threadIdx.x;
    int tx = tid & 15, ty = tid >> 4;

    float acc[8][8];
#pragma unroll
    for (int i = 0; i < 8; i++)
#pragma unroll
        for (int j = 0; j < 8; j++) acc[i][j] = 0.f;

    for (int k0 = 0; k0 < 128; k0 += 32) {
#pragma unroll
        for (int m = 0; m < 4; m++) {
            int l4 = tid + m * 256;           // 0..1023 float4 slots
            int r = l4 >> 3, c = l4 & 7;      // x: row r, k-quad c
            int gr = row0 + r;
            float4 v = make_float4(0.f, 0.f, 0.f, 0.f);
            if (gr < n) v = *(const float4*)(x + (size_t)gr * 128 + k0 + 4 * c);
            xs[4 * c + 0][r] = v.x;
            xs[4 * c + 1][r] = v.y;
            xs[4 * c + 2][r] = v.z;
            xs[4 * c + 3][r] = v.w;

            int kk = l4 >> 5, c4 = l4 & 31;   // W: k-row kk, col-quad c4
            float4 wv = *(const float4*)(W + (size_t)(k0 + kk) * 128 + 4 * c4);
            *(float4*)&ws[kk][4 * c4] = wv;
        }
        __syncthreads();
#pragma unroll
        for (int kk = 0; kk < 32; kk++) {
            float a[8], bb[8];
#pragma unroll
            for (int i = 0; i < 8; i++) a[i] = xs[kk][ty * 8 + i];
#pragma unroll
            for (int j = 0; j < 8; j++) bb[j] = ws[kk][tx * 8 + j];
#pragma unroll
            for (int i = 0; i < 8; i++)
#pragma unroll
                for (int j = 0; j < 8; j++) acc[i][j] += a[i] * bb[j];
        }
        __syncthreads();
    }
#pragma unroll
    for (int i = 0; i < 8; i++) {
        int gr = row0 + ty * 8 + i;
        if (gr < n) {
#pragma unroll
            for (int j = 0; j < 8; j++) {
                int col = tx * 8 + j;
                out[(size_t)gr * 128 + col] = acc[i][j] + b[col];
            }
        }
    }
}

// ---------------------------------------------------------------------------
// CSR build: zero -> histogram -> scan -> scatter
// ---------------------------------------------------------------------------
__global__ void zero_deg_kernel(int n) {
    int i = blockIdx.x * blockDim.x + threadIdx.x;
    if (i < n) g_deg[i] = 0;
}

__global__ void hist_kernel(const int* __restrict__ dst, int e) {
    int i = blockIdx.x * blockDim.x + threadIdx.x;
    if (i < e) atomicAdd(&g_deg[dst[i]], 1);
}

__global__ void scan_kernel(int n) {
    __shared__ int ssum[1024];
    int t = threadIdx.x;
    int chunk = (n + 1023) >> 10;
    int b0 = t * chunk;
    int b1 = min(b0 + chunk, n);
    int s = 0;
    for (int i = b0; i < b1; i++) s += g_deg[i];
    ssum[t] = s;
    __syncthreads();
    for (int off = 1; off < 1024; off <<= 1) {
        int v = (t >= off) ? ssum[t - off] : 0;
        __syncthreads();
        ssum[t] += v;
        __syncthreads();
    }
    int pre = (t == 0) ? 0 : ssum[t - 1];
    for (int i = b0; i < b1; i++) {
        g_off[i] = pre;
        g_ptr[i] = pre;
        pre += g_deg[i];
    }
    if (t == 1023) g_off[n] = ssum[1023];
}

__global__ void scatter_kernel(const int* __restrict__ src, const int* __restrict__ dst, int e) {
    int i = blockIdx.x * blockDim.x + threadIdx.x;
    if (i < e) {
        int d = dst[i];
        int pos = atomicAdd(&g_ptr[d], 1);
        g_csr[pos] = src[i];
    }
}

// ---------------------------------------------------------------------------
// Node-centric fused GATv2: one block per dst node, 4 warps = 4 heads.
// Online softmax over incoming edges, then LayerNorm + ELU epilogue.
// ---------------------------------------------------------------------------
__global__ void __launch_bounds__(128) gat_node_kernel(
    const float* __restrict__ attn, const float* __restrict__ out_bias,
    const float* __restrict__ lnw, const float* __restrict__ lnb,
    float* __restrict__ out, int n) {
    int node = blockIdx.x;
    int tid = threadIdx.x;       // 0..127; == h*32 + lane
    int lane = tid & 31;
    int h = tid >> 5;

    float attnv = attn[tid];                       // attn is [H,D] contiguous
    float fdv = g_fd[(size_t)node * 128 + tid];

    int r0 = g_off[node];
    int r1 = g_off[node + 1];

    float m = -INFINITY, den = 0.f, acc = 0.f;

    for (int i0 = r0; i0 < r1; i0 += 32) {
        int cnt = min(32, r1 - i0);
        int sidx = (lane < cnt) ? __ldg(&g_csr[i0 + lane]) : 0;
        for (int j = 0; j < cnt; j++) {
            int s = __shfl_sync(0xffffffffu, sidx, j);
            float v = __ldg(&g_fs[(size_t)s * 128 + tid]);
            float t = v + fdv;
            t = (t > 0.f) ? t : 0.2f * t;          // leaky_relu
            float p = t * attnv;
#pragma unroll
            for (int d2 = 16; d2; d2 >>= 1) p += __shfl_xor_sync(0xffffffffu, p, d2);
            // p = logit for (edge, head h); online softmax update
            if (p > m) {
                float sc = __expf(m - p);          // exp(-inf)=0 on first iter
                den *= sc;
                acc *= sc;
                m = p;
            }
            float ee = __expf(p - m);
            den += ee;
            acc += ee * v;
        }
    }

    float rst = (den > 0.f) ? acc / den : 0.f;
    float hval = rst + out_bias[tid];

    // LayerNorm over the 128 features of this node
    __shared__ float red[8];
    float s1 = hval, s2 = hval * hval;
#pragma unroll
    for (int d2 = 16; d2; d2 >>= 1) {
        s1 += __shfl_xor_sync(0xffffffffu, s1, d2);
        s2 += __shfl_xor_sync(0xffffffffu, s2, d2);
    }
    if (lane == 0) {
        red[h] = s1;
        red[4 + h] = s2;
    }
    __syncthreads();
    s1 = red[0] + red[1] + red[2] + red[3];
    s2 = red[4] + red[5] + red[6] + red[7];
    float mean = s1 * (1.f / 128.f);
    float var = s2 * (1.f / 128.f) - mean * mean;
    if (var < 0.f) var = 0.f;
    float inv = rsqrtf(var + 1e-12f);
    float y = (hval - mean) * inv * lnw[tid] + lnb[tid];
    out[(size_t)node * 128 + tid] = (y > 0.f) ? y : expm1f(y);   // ELU
}

// ---------------------------------------------------------------------------
extern "C" void kernel_launch(void* const* d_in, const int* in_sizes, int n_in,
                              void* d_out, int out_size) {
    const float* x        = (const float*)d_in[0];
    const float* Wsrc     = (const float*)d_in[1];
    const float* bsrc     = (const float*)d_in[2];
    const float* Wdst     = (const float*)d_in[3];
    const float* bdst     = (const float*)d_in[4];
    const float* attn     = (const float*)d_in[5];
    const float* out_bias = (const float*)d_in[6];
    const float* lnw      = (const float*)d_in[7];
    const float* lnb      = (const float*)d_in[8];
    const int*   src      = (const int*)d_in[9];
    const int*   dst      = (const int*)d_in[10];

    int n = in_sizes[0] / 128;
    int e = in_sizes[9];

    dim3 gg((n + 127) / 128, 2);
    sgemm_kernel<<<gg, 256>>>(x, Wsrc, bsrc, Wdst, bdst, n);
    zero_deg_kernel<<<(n + 255) / 256, 256>>>(n);
    hist_kernel<<<(e + 255) / 256, 256>>>(dst, e);
    scan_kernel<<<1, 1024>>>(n);
    scatter_kernel<<<(e + 255) / 256, 256>>>(src, dst, e);
    gat_node_kernel<<<n, 128>>>(attn, out_bias, lnw, lnb, (float*)d_out, n);
}

// round 3
// speedup vs baseline: 1.2736x; 1.2736x over previous
#include <cuda_runtime.h>
#include <math.h>

#define NMAX 50000
#define EMAX 800000
#define SCAN_BLK 1024
#define NB_MAX 64

// scratch (device globals — no allocation allowed)
__device__ float g_fs[NMAX * 128];
__device__ float g_fd[NMAX * 128];
__device__ int   g_deg[NMAX];
__device__ int   g_off[NMAX + 1];
__device__ int   g_ptr[NMAX];
__device__ int   g_csr[EMAX];
__device__ int   g_bsum[NB_MAX];
__device__ int   g_boff[NB_MAX];

// ---------------------------------------------------------------------------
// Fused: SGEMM (out = x@W+b for fs and fd) + dst histogram.
// Blocks [0, nbg)        -> fs gemm
// Blocks [nbg, 2*nbg)    -> fd gemm
// Blocks [2*nbg, ...)    -> grid-stride histogram over edges
// 256 threads. GEMM: tile 128x128, 8x8 per thread, k-chunks of 32.
// ---------------------------------------------------------------------------
__global__ void __launch_bounds__(256) fused_gemm_hist_kernel(
    const float* __restrict__ x,
    const float* __restrict__ Wsrc, const float* __restrict__ bsrc,
    const float* __restrict__ Wdst, const float* __restrict__ bdst,
    const int* __restrict__ dst,
    int n, int e, int nbg, int nhist) {
    int bid = blockIdx.x;

    if (bid >= 2 * nbg) {
        // ---- histogram path ----
        int hb = bid - 2 * nbg;
        int stride = nhist * 256;
        for (int i = hb * 256 + threadIdx.x; i < e; i += stride)
            atomicAdd(&g_deg[dst[i]], 1);
        return;
    }

    // ---- gemm path ----
    const float* W = (bid < nbg) ? Wsrc : Wdst;
    const float* b = (bid < nbg) ? bsrc : bdst;
    float* out = (bid < nbg) ? g_fs : g_fd;
    int row0 = ((bid < nbg) ? bid : bid - nbg) * 128;

    __shared__ float xs[32][132];  // [k][row], padded
    __shared__ float ws[32][132];  // [k][col], padded

    int tid = threadIdx.x;
    int tx = tid & 15, ty = tid >> 4;

    float acc[8][8];
#pragma unroll
    for (int i = 0; i < 8; i++)
#pragma unroll
        for (int j = 0; j < 8; j++) acc[i][j] = 0.f;

    for (int k0 = 0; k0 < 128; k0 += 32) {
#pragma unroll
        for (int m = 0; m < 4; m++) {
            int l4 = tid + m * 256;           // 0..1023 float4 slots
            int r = l4 >> 3, c = l4 & 7;      // x: row r, k-quad c
            int gr = row0 + r;
            float4 v = make_float4(0.f, 0.f, 0.f, 0.f);
            if (gr < n) v = *(const float4*)(x + (size_t)gr * 128 + k0 + 4 * c);
            xs[4 * c + 0][r] = v.x;
            xs[4 * c + 1][r] = v.y;
            xs[4 * c + 2][r] = v.z;
            xs[4 * c + 3][r] = v.w;

            int kk = l4 >> 5, c4 = l4 & 31;   // W: k-row kk, col-quad c4
            float4 wv = *(const float4*)(W + (size_t)(k0 + kk) * 128 + 4 * c4);
            *(float4*)&ws[kk][4 * c4] = wv;
        }
        __syncthreads();
#pragma unroll
        for (int kk = 0; kk < 32; kk++) {
            float a[8], bb[8];
#pragma unroll
            for (int i = 0; i < 8; i++) a[i] = xs[kk][ty * 8 + i];
#pragma unroll
            for (int j = 0; j < 8; j++) bb[j] = ws[kk][tx * 8 + j];
#pragma unroll
            for (int i = 0; i < 8; i++)
#pragma unroll
                for (int j = 0; j < 8; j++) acc[i][j] += a[i] * bb[j];
        }
        __syncthreads();
    }
#pragma unroll
    for (int i = 0; i < 8; i++) {
        int gr = row0 + ty * 8 + i;
        if (gr < n) {
#pragma unroll
            for (int j = 0; j < 8; j++) {
                int col = tx * 8 + j;
                out[(size_t)gr * 128 + col] = acc[i][j] + b[col];
            }
        }
    }
}

// ---------------------------------------------------------------------------
// Multi-block exclusive scan of g_deg -> g_off (+ g_ptr copy)
// ---------------------------------------------------------------------------
__global__ void zero_deg_kernel(int n) {
    int i = blockIdx.x * blockDim.x + threadIdx.x;
    if (i < n) g_deg[i] = 0;
}

// Phase A: per-block inclusive scan; write local-exclusive to g_off, block sum.
__global__ void __launch_bounds__(SCAN_BLK) scanA_kernel(int n) {
    __shared__ int s[SCAN_BLK];
    int t = threadIdx.x;
    int i = blockIdx.x * SCAN_BLK + t;
    int v = (i < n) ? g_deg[i] : 0;
    s[t] = v;
    __syncthreads();
#pragma unroll
    for (int off = 1; off < SCAN_BLK; off <<= 1) {
        int u = (t >= off) ? s[t - off] : 0;
        __syncthreads();
        s[t] += u;
        __syncthreads();
    }
    if (i < n) g_off[i] = s[t] - v;   // exclusive (local)
    if (t == SCAN_BLK - 1) g_bsum[blockIdx.x] = s[t];
}

// Phase B: scan the block sums (<= NB_MAX of them). 1 block, NB_MAX threads.
__global__ void scanB_kernel(int nb) {
    __shared__ int s[NB_MAX];
    int t = threadIdx.x;
    int v = (t < nb) ? g_bsum[t] : 0;
    s[t] = v;
    __syncthreads();
#pragma unroll
    for (int off = 1; off < NB_MAX; off <<= 1) {
        int u = (t >= off) ? s[t - off] : 0;
        __syncthreads();
        s[t] += u;
        __syncthreads();
    }
    if (t < nb) g_boff[t] = s[t] - v;  // exclusive
}

// Phase C: add block offsets; init g_ptr; set sentinel.
__global__ void __launch_bounds__(SCAN_BLK) scanC_kernel(int n, int e) {
    int i = blockIdx.x * SCAN_BLK + threadIdx.x;
    if (i < n) {
        int o = g_off[i] + g_boff[blockIdx.x];
        g_off[i] = o;
        g_ptr[i] = o;
    }
    if (i == 0) g_off[n] = e;
}

__global__ void scatter_kernel(const int* __restrict__ src, const int* __restrict__ dst, int e) {
    int i = blockIdx.x * blockDim.x + threadIdx.x;
    if (i < e) {
        int d = dst[i];
        int pos = atomicAdd(&g_ptr[d], 1);
        g_csr[pos] = src[i];
    }
}

// ---------------------------------------------------------------------------
// Node-centric fused GATv2: one block per dst node, 4 warps = 4 heads.
// Online softmax over incoming edges, then LayerNorm + ELU epilogue.
// ---------------------------------------------------------------------------
__global__ void __launch_bounds__(128) gat_node_kernel(
    const float* __restrict__ attn, const float* __restrict__ out_bias,
    const float* __restrict__ lnw, const float* __restrict__ lnb,
    float* __restrict__ out, int n) {
    int node = blockIdx.x;
    int tid = threadIdx.x;       // 0..127; == h*32 + lane
    int lane = tid & 31;
    int h = tid >> 5;

    float attnv = attn[tid];                       // attn is [H,D] contiguous
    float fdv = g_fd[(size_t)node * 128 + tid];

    int r0 = g_off[node];
    int r1 = g_off[node + 1];

    float m = -INFINITY, den = 0.f, acc = 0.f;

    for (int i0 = r0; i0 < r1; i0 += 32) {
        int cnt = min(32, r1 - i0);
        int sidx = (lane < cnt) ? __ldg(&g_csr[i0 + lane]) : 0;
        for (int j = 0; j < cnt; j++) {
            int s = __shfl_sync(0xffffffffu, sidx, j);
            float v = __ldg(&g_fs[(size_t)s * 128 + tid]);
            float t = v + fdv;
            t = (t > 0.f) ? t : 0.2f * t;          // leaky_relu
            float p = t * attnv;
#pragma unroll
            for (int d2 = 16; d2; d2 >>= 1) p += __shfl_xor_sync(0xffffffffu, p, d2);
            // p = logit for (edge, head h); online softmax update
            if (p > m) {
                float sc = __expf(m - p);          // exp(-inf)=0 on first iter
                den *= sc;
                acc *= sc;
                m = p;
            }
            float ee = __expf(p - m);
            den += ee;
            acc += ee * v;
        }
    }

    float rst = (den > 0.f) ? acc / den : 0.f;
    float hval = rst + out_bias[tid];

    // LayerNorm over the 128 features of this node
    __shared__ float red[8];
    float s1 = hval, s2 = hval * hval;
#pragma unroll
    for (int d2 = 16; d2; d2 >>= 1) {
        s1 += __shfl_xor_sync(0xffffffffu, s1, d2);
        s2 += __shfl_xor_sync(0xffffffffu, s2, d2);
    }
    if (lane == 0) {
        red[h] = s1;
        red[4 + h] = s2;
    }
    __syncthreads();
    s1 = red[0] + red[1] + red[2] + red[3];
    s2 = red[4] + red[5] + red[6] + red[7];
    float mean = s1 * (1.f / 128.f);
    float var = s2 * (1.f / 128.f) - mean * mean;
    if (var < 0.f) var = 0.f;
    float inv = rsqrtf(var + 1e-12f);
    float y = (hval - mean) * inv * lnw[tid] + lnb[tid];
    out[(size_t)node * 128 + tid] = (y > 0.f) ? y : expm1f(y);   // ELU
}

// ---------------------------------------------------------------------------
extern "C" void kernel_launch(void* const* d_in, const int* in_sizes, int n_in,
                              void* d_out, int out_size) {
    const float* x        = (const float*)d_in[0];
    const float* Wsrc     = (const float*)d_in[1];
    const float* bsrc     = (const float*)d_in[2];
    const float* Wdst     = (const float*)d_in[3];
    const float* bdst     = (const float*)d_in[4];
    const float* attn     = (const float*)d_in[5];
    const float* out_bias = (const float*)d_in[6];
    const float* lnw      = (const float*)d_in[7];
    const float* lnb      = (const float*)d_in[8];
    const int*   src      = (const int*)d_in[9];
    const int*   dst      = (const int*)d_in[10];

    int n = in_sizes[0] / 128;
    int e = in_sizes[9];

    int nbg = (n + 127) / 128;          // gemm blocks per matrix
    int nhist = 256;                    // grid-stride histogram blocks
    int nb_scan = (n + SCAN_BLK - 1) / SCAN_BLK;

    zero_deg_kernel<<<(n + 255) / 256, 256>>>(n);
    fused_gemm_hist_kernel<<<2 * nbg + nhist, 256>>>(x, Wsrc, bsrc, Wdst, bdst,
                                                     dst, n, e, nbg, nhist);
    scanA_kernel<<<nb_scan, SCAN_BLK>>>(n);
    scanB_kernel<<<1, NB_MAX>>>(nb_scan);
    scanC_kernel<<<nb_scan, SCAN_BLK>>>(n, e);
    scatter_kernel<<<(e + 255) / 256, 256>>>(src, dst, e);
    gat_node_kernel<<<n, 128>>>(attn, out_bias, lnw, lnb, (float*)d_out, n);
}